// round 9
// baseline (speedup 1.0000x reference)
#include <cuda_runtime.h>
#include <cuda_bf16.h>
#include <cstdint>

// Problem constants
#define B_  4
#define C_  256
#define H_  64
#define W_  64
#define O_  256
#define K2_ 9
#define PAD_ 2
#define DIL_ 2
#define CK_ (C_ * K2_)            // 2304
#define HW_ (H_ * W_)             // 4096
#define OUT_MAIN (B_ * O_ * HW_)  // 4194304
#define DW_ELEMS (O_ * C_ * K2_)  // 589824

#define SWZ(off) ((off) ^ (((off) >> 3) & 0x70))

// ---------------------------------------------------------------------------
// Scratch (device globals; no allocation allowed)
// ---------------------------------------------------------------------------
__device__ float g_off[B_ * 18 * HW_];            // clipped offsets (B,18,H,W)
__device__ float g_xT[B_ * HW_ * C_];             // x transposed: [b][hw][c]
__device__ unsigned char g_w[36 * 65536];         // bf16 hi/lo weight tiles, pre-swizzled

// ---------------------------------------------------------------------------
// helpers
// ---------------------------------------------------------------------------
__device__ __forceinline__ void ldsm4(uint32_t* r, uint32_t addr) {
    asm volatile("ldmatrix.sync.aligned.m8n8.x4.shared.b16 {%0,%1,%2,%3}, [%4];"
        : "=r"(r[0]), "=r"(r[1]), "=r"(r[2]), "=r"(r[3]) : "r"(addr));
}
__device__ __forceinline__ void mma16816(float* c, const uint32_t* a, const uint32_t* b) {
    asm volatile("mma.sync.aligned.m16n8k16.row.col.f32.bf16.bf16.f32 "
        "{%0,%1,%2,%3}, {%4,%5,%6,%7}, {%8,%9}, {%0,%1,%2,%3};"
        : "+f"(c[0]), "+f"(c[1]), "+f"(c[2]), "+f"(c[3])
        : "r"(a[0]), "r"(a[1]), "r"(a[2]), "r"(a[3]), "r"(b[0]), "r"(b[1]));
}
__device__ __forceinline__ uint32_t smem_u32(const void* p) {
    uint32_t a;
    asm("{ .reg .u64 t; cvta.to.shared.u64 t, %1; cvt.u32.u64 %0, t; }"
        : "=r"(a) : "l"(p));
    return a;
}
__device__ __forceinline__ uint32_t pack_bf16(float a, float b) {
    return ((uint32_t)__bfloat16_as_ushort(__float2bfloat16(b)) << 16) |
           (uint32_t)__bfloat16_as_ushort(__float2bfloat16(a));
}
__device__ __forceinline__ void cpasync16(uint32_t dst, const void* src) {
    asm volatile("cp.async.cg.shared.global [%0], [%1], 16;"
        :: "r"(dst), "l"(src) : "memory");
}

// ---------------------------------------------------------------------------
// Merged prologue kernel: roles by blockIdx.x (all 256 threads)
// ---------------------------------------------------------------------------
#define NB_T 4096
#define NB_O 256
#define NB_P 2304
#define PRO_SMEM 41472

__global__ __launch_bounds__(256) void prologue_kernel(
    const float* __restrict__ x, const float* __restrict__ ow,
    const float* __restrict__ ob, const float* __restrict__ dw,
    float* __restrict__ out_tail)
{
    extern __shared__ float sm[];
    const int bid = blockIdx.x;
    const int tid = threadIdx.x;

    if (bid < NB_T) {
        // ---- transpose ----
        __shared__ float ts[32][33];
        const int b = bid >> 10;
        const int tile = bid & 1023;
        const int c0 = (tile >> 7) * 32;
        const int hw0 = (tile & 127) * 32;
        const int tx = tid & 31, ty = tid >> 5;
        const float* xb = x + (size_t)b * C_ * HW_;
#pragma unroll
        for (int i = 0; i < 4; i++)
            ts[ty + i * 8][tx] = __ldg(xb + (size_t)(c0 + ty + i * 8) * HW_ + hw0 + tx);
        __syncthreads();
        float* dst = g_xT + (size_t)b * HW_ * C_;
#pragma unroll
        for (int i = 0; i < 4; i++)
            dst[(size_t)(hw0 + ty + i * 8) * C_ + c0 + tx] = ts[tx][ty + i * 8];
        return;
    }

    if (bid < NB_T + NB_O) {
        // ---- offset conv ----
        const int b2 = bid - NB_T;
        const int b = b2 >> 6;
        const int h = b2 & 63;
        const int g = tid >> 5;       // 0..7
        const int wq = tid & 31;
        const int w0 = wq * 2;

        float acc[18][2];
#pragma unroll
        for (int ch = 0; ch < 18; ch++) { acc[ch][0] = 0.f; acc[ch][1] = 0.f; }

        for (int r = 0; r < 4; r++) {
            __syncthreads();
            for (int i = tid; i < 64 * 162; i += 256) {
                int cc = i / 162;
                int j  = i - cc * 162;
                int ch = j / 9;
                int t  = j - ch * 9;
                sm[i] = ow[ch * CK_ + (r * 64 + cc) * 9 + t];
            }
            __syncthreads();

#pragma unroll
            for (int q = 0; q < 8; q++) {
                const int cc = g * 8 + q;
                const int c  = r * 64 + cc;
                const float* xp = x + ((size_t)b * C_ + c) * HW_;
                float xv[3][4];
#pragma unroll
                for (int ry = 0; ry < 3; ry++) {
                    int yy = h - 1 + ry;
                    bool yok = (yy >= 0) & (yy < H_);
#pragma unroll
                    for (int cx = 0; cx < 4; cx++) {
                        int xx = w0 - 1 + cx;
                        bool ok = yok & (xx >= 0) & (xx < W_);
                        xv[ry][cx] = ok ? __ldg(xp + yy * W_ + xx) : 0.0f;
                    }
                }
                const float* wc = sm + cc * 162;
#pragma unroll
                for (int ch = 0; ch < 18; ch++) {
#pragma unroll
                    for (int ky = 0; ky < 3; ky++) {
#pragma unroll
                        for (int kx = 0; kx < 3; kx++) {
                            float wv = wc[ch * 9 + ky * 3 + kx];
                            acc[ch][0] = fmaf(wv, xv[ky][kx],     acc[ch][0]);
                            acc[ch][1] = fmaf(wv, xv[ky][kx + 1], acc[ch][1]);
                        }
                    }
                }
            }
        }
        __syncthreads();
#pragma unroll
        for (int ch = 0; ch < 18; ch++) {
            sm[(g * 18 + ch) * 64 + w0]     = acc[ch][0];
            sm[(g * 18 + ch) * 64 + w0 + 1] = acc[ch][1];
        }
        __syncthreads();
        for (int i = tid; i < 18 * 64; i += 256) {
            int ch = i >> 6;
            int w  = i & 63;
            float s = ob[ch];
#pragma unroll
            for (int gg = 0; gg < 8; gg++) s += sm[(gg * 18 + ch) * 64 + w];
            s = fminf(fmaxf(s, -1.0f), 1.0f);
            g_off[((size_t)b * 18 + ch) * HW_ + h * W_ + w] = s;
        }
        return;
    }

    // ---- weight prep + tail copy ----
    {
        int id = (bid - NB_T - NB_O) * 256 + tid;
        out_tail[id] = dw[id];
        int k = id & 63;
        int o = (id >> 6) & 255;
        int t = id >> 14;            // 0..35
        int n = t >> 2;
        int cc = t & 3;
        int c = cc * 64 + k;
        float v = __ldg(dw + o * CK_ + c * 9 + n);
        __nv_bfloat16 hi = __float2bfloat16(v);
        __nv_bfloat16 lo = __float2bfloat16(v - __bfloat162float(hi));
        uint32_t sw = SWZ((uint32_t)(o * 128 + k * 2));
        size_t base = (size_t)t * 65536;
        *(__nv_bfloat16*)(g_w + base + sw)         = hi;
        *(__nv_bfloat16*)(g_w + base + 32768 + sw) = lo;
    }
}

// ---------------------------------------------------------------------------
// Fused deform sampling + bf16-split mma.sync GEMM.
// Grid = 256 blocks (b, h): N=64 pixels (1 row), M=256 o, K=2304 (36 x 64).
// 256 threads (8 warps, warp tile 64x32), 2 CTAs/SM for cross-CTA overlap.
// A single-buffered (cp.async reload at chunk boundary, hidden by peer CTA);
// B double-buffered, gathered/packed in-loop overlapped with MMA.
// ---------------------------------------------------------------------------
#define OFF_A    0        // [2 comp][256][64] bf16 = 65536
#define OFF_B    65536    // 2 buf x [2 comp][64][64] bf16 = 2 x 16384
#define OFF_SWT  98304    // float [9*64][4]  = 9216
#define OFF_SIDX 107520   // short [9*64][4]  = 4608
#define FUSED_SMEM 112128

__global__ __launch_bounds__(256, 2) void fused_deform_mma_kernel(
    const float* __restrict__ db, float* __restrict__ out)
{
    extern __shared__ char smem[];
    const uint32_t sb = smem_u32(smem);
    const int tid = threadIdx.x;
    const int wid = tid >> 5;
    const int lid = tid & 31;
    const int b = blockIdx.x >> 6;
    const int h = blockIdx.x & 63;

    // ---- sampling metadata: 9 taps x 64 pixels ----
    float* swt  = (float*)(smem + OFF_SWT);
    short* sidx = (short*)(smem + OFF_SIDX);
    for (int task = tid; task < 9 * 64; task += 256) {
        int n = task >> 6;
        int w = task & 63;
        float dy = g_off[((size_t)b * 18 + 2 * n)     * HW_ + h * W_ + w];
        float dx = g_off[((size_t)b * 18 + 2 * n + 1) * HW_ + h * W_ + w];
        float py = dy + (float)(-PAD_ + (n / 3) * DIL_ + h);
        float px = dx + (float)(-PAD_ + (n % 3) * DIL_ + w);
        float y0f = floorf(py);
        float x0f = floorf(px);
        float ly1 = py - y0f, lx1 = px - x0f;
        float ly0 = 1.0f - ly1, lx0 = 1.0f - lx1;
        int y0 = (int)y0f, x0 = (int)x0f;
#pragma unroll
        for (int j = 0; j < 4; j++) {
            int yy = y0 + (j >> 1);
            int xx = x0 + (j & 1);
            float wgt = ((j >> 1) ? ly1 : ly0) * ((j & 1) ? lx1 : lx0);
            bool ok = (yy >= 0) & (yy < H_) & (xx >= 0) & (xx < W_);
            int yi = min(max(yy, 0), H_ - 1);
            int xi = min(max(xx, 0), W_ - 1);
            sidx[task * 4 + j] = (short)(yi * W_ + xi);
            swt [task * 4 + j] = ok ? wgt : 0.0f;
        }
    }

    const float* xT = g_xT + (size_t)b * HW_ * C_;
    const int ch4 = tid & 15;          // channel group of 4 (fixed per thread)
    const int pixB = tid >> 4;         // base pixel 0..15

    const int wm = wid >> 1;           // 0..3 : o block of 64
    const int wn = wid & 1;            // 0..1 : pixel block of 32
    const int aRow = wm * 64 + (lid & 15);
    const int aKad = (lid >> 4) * 16;
    const int bRow = wn * 32 + ((lid >> 4) & 1) * 8 + (lid & 7);
    const int bKad = ((lid >> 3) & 1) * 16;

    float acc[4][4][4];
#pragma unroll
    for (int i = 0; i < 4; i++)
#pragma unroll
        for (int j = 0; j < 4; j++)
#pragma unroll
            for (int q = 0; q < 4; q++) acc[i][j][q] = 0.0f;

    // ---- prologue: A(0) via cp.async; B(0) gather ----
    {
        uint32_t dstA = sb + OFF_A;
        const char* srcA = (const char*)g_w;
#pragma unroll
        for (int i = 0; i < 16; i++)
            cpasync16(dstA + (tid + i * 256) * 16, srcA + (size_t)(tid + i * 256) * 16);
        asm volatile("cp.async.commit_group;" ::: "memory");

#pragma unroll
        for (int it = 0; it < 4; it++) {
            int id = tid + it * 256;          // 1024 tasks: 64 px x 16 ch-groups
            int c4 = id & 15;
            int p  = id >> 4;
            const float4 wt = *(const float4*)(swt + p * 4);
            const short* si = sidx + p * 4;
            const float* xb = xT + c4 * 4;
            float4 v0 = __ldg((const float4*)(xb + ((int)si[0] << 8)));
            float4 v1 = __ldg((const float4*)(xb + ((int)si[1] << 8)));
            float4 v2 = __ldg((const float4*)(xb + ((int)si[2] << 8)));
            float4 v3 = __ldg((const float4*)(xb + ((int)si[3] << 8)));
            float s0 = wt.x * v0.x + wt.y * v1.x + wt.z * v2.x + wt.w * v3.x;
            float s1 = wt.x * v0.y + wt.y * v1.y + wt.z * v2.y + wt.w * v3.y;
            float s2 = wt.x * v0.z + wt.y * v1.z + wt.z * v2.z + wt.w * v3.z;
            float s3 = wt.x * v0.w + wt.y * v1.w + wt.z * v2.w + wt.w * v3.w;
            uint32_t h0 = pack_bf16(s0, s1), h1 = pack_bf16(s2, s3);
            float r0 = s0 - __bfloat162float(__float2bfloat16(s0));
            float r1 = s1 - __bfloat162float(__float2bfloat16(s1));
            float r2 = s2 - __bfloat162float(__float2bfloat16(s2));
            float r3 = s3 - __bfloat162float(__float2bfloat16(s3));
            uint32_t l0 = pack_bf16(r0, r1), l1 = pack_bf16(r2, r3);
            uint32_t sw = SWZ((uint32_t)(p * 128 + c4 * 8));
            *(uint2*)(smem + OFF_B + sw)        = make_uint2(h0, h1);
            *(uint2*)(smem + OFF_B + 8192 + sw) = make_uint2(l0, l1);
        }
        asm volatile("cp.async.wait_group 0;" ::: "memory");
        __syncthreads();
    }

    const uint32_t aBaseH = sb + OFF_A;
    const uint32_t aBaseL = aBaseH + 32768;

    for (int t = 0; t < 36; t++) {
        const uint32_t bufT = (uint32_t)(t & 1);
        const bool more = (t < 35);

        const uint32_t bBaseH = sb + OFF_B + bufT * 16384;
        const uint32_t bBaseL = bBaseH + 8192;
        char* bDst = smem + OFF_B + (bufT ^ 1) * 16384;

        const int nN = (t + 1) >> 2;
        const int cN = ((t + 1) & 3) * 64;

        // 4 phases: gather B(t+1) issue -> MMA kstep(t) -> pack/STS B(t+1)
#pragma unroll
        for (int ph = 0; ph < 4; ph++) {
            float4 v0, v1, v2, v3; float4 wt;
            int p = (pixB + ph * 16) & 63;
            if (more) {
                int task = nN * 64 + p;
                wt = *(const float4*)(swt + task * 4);
                const short* si = sidx + task * 4;
                const float* xb = xT + cN + ch4 * 4;
                v0 = __ldg((const float4*)(xb + ((int)si[0] << 8)));
                v1 = __ldg((const float4*)(xb + ((int)si[1] << 8)));
                v2 = __ldg((const float4*)(xb + ((int)si[2] << 8)));
                v3 = __ldg((const float4*)(xb + ((int)si[3] << 8)));
            }

            // MMA k-step ph of chunk t
            {
                uint32_t bh[8], bl[8];
#pragma unroll
                for (int pair = 0; pair < 2; pair++) {
                    uint32_t off = SWZ((uint32_t)((bRow + pair * 16) * 128 + ph * 32 + bKad));
                    ldsm4(bh + pair * 4, bBaseH + off);
                    ldsm4(bl + pair * 4, bBaseL + off);
                }
#pragma unroll
                for (int mt = 0; mt < 4; mt++) {
                    uint32_t offA = SWZ((uint32_t)((aRow + mt * 16) * 128 + ph * 32 + aKad));
                    uint32_t ah[4], al[4];
                    ldsm4(ah, aBaseH + offA);
#pragma unroll
                    for (int j = 0; j < 4; j++) {
                        mma16816(acc[mt][j], ah, bh + j * 2);
                        mma16816(acc[mt][j], ah, bl + j * 2);
                    }
                    ldsm4(al, aBaseL + offA);
#pragma unroll
                    for (int j = 0; j < 4; j++)
                        mma16816(acc[mt][j], al, bh + j * 2);
                }
            }

            if (more) {
                float s0 = wt.x * v0.x + wt.y * v1.x + wt.z * v2.x + wt.w * v3.x;
                float s1 = wt.x * v0.y + wt.y * v1.y + wt.z * v2.y + wt.w * v3.y;
                float s2 = wt.x * v0.z + wt.y * v1.z + wt.z * v2.z + wt.w * v3.z;
                float s3 = wt.x * v0.w + wt.y * v1.w + wt.z * v2.w + wt.w * v3.w;
                uint32_t h0 = pack_bf16(s0, s1), h1 = pack_bf16(s2, s3);
                float r0 = s0 - __bfloat162float(__float2bfloat16(s0));
                float r1 = s1 - __bfloat162float(__float2bfloat16(s1));
                float r2 = s2 - __bfloat162float(__float2bfloat16(s2));
                float r3 = s3 - __bfloat162float(__float2bfloat16(s3));
                uint32_t l0 = pack_bf16(r0, r1), l1 = pack_bf16(r2, r3);
                uint32_t sw = SWZ((uint32_t)(p * 128 + ch4 * 8));
                *(uint2*)(bDst + sw)        = make_uint2(h0, h1);
                *(uint2*)(bDst + 8192 + sw) = make_uint2(l0, l1);
            }
        }

        // chunk boundary: reload single-buffered A
        __syncthreads();   // all warps done reading A(t) and B(t); B(t+1) written
        if (more) {
            uint32_t dstA = sb + OFF_A;
            const char* srcA = (const char*)(g_w + (size_t)(t + 1) * 65536);
#pragma unroll
            for (int i = 0; i < 16; i++)
                cpasync16(dstA + (tid + i * 256) * 16, srcA + (size_t)(tid + i * 256) * 16);
            asm volatile("cp.async.commit_group;" ::: "memory");
            asm volatile("cp.async.wait_group 0;" ::: "memory");
            __syncthreads();   // A(t+1) visible everywhere
        }
    }

    // ---- epilogue: bias + store ----
#pragma unroll
    for (int mt = 0; mt < 4; mt++) {
        int o0 = wm * 64 + mt * 16 + (lid >> 2);
        float b0v = __ldg(db + o0);
        float b1v = __ldg(db + o0 + 8);
#pragma unroll
        for (int j = 0; j < 4; j++) {
            int col = wn * 32 + j * 8 + (lid & 3) * 2;
            float* p0 = out + ((size_t)(b * O_ + o0)) * HW_ + (size_t)h * W_ + col;
            *(float2*)p0 = make_float2(acc[mt][j][0] + b0v, acc[mt][j][1] + b0v);
            float* p1 = p0 + (size_t)8 * HW_;
            *(float2*)p1 = make_float2(acc[mt][j][2] + b1v, acc[mt][j][3] + b1v);
        }
    }
}

// ---------------------------------------------------------------------------
extern "C" void kernel_launch(void* const* d_in, const int* in_sizes, int n_in,
                              void* d_out, int out_size)
{
    const float* x  = (const float*)d_in[0];
    const float* ow = (const float*)d_in[1];
    const float* ob = (const float*)d_in[2];
    const float* dw = (const float*)d_in[3];
    const float* db = (const float*)d_in[4];
    float* out = (float*)d_out;

    cudaFuncSetAttribute(prologue_kernel,
                         cudaFuncAttributeMaxDynamicSharedMemorySize, PRO_SMEM);
    cudaFuncSetAttribute(fused_deform_mma_kernel,
                         cudaFuncAttributeMaxDynamicSharedMemorySize, FUSED_SMEM);

    prologue_kernel<<<NB_T + NB_O + NB_P, 256, PRO_SMEM>>>(x, ow, ob, dw, out + OUT_MAIN);
    fused_deform_mma_kernel<<<B_ * H_, 256, FUSED_SMEM>>>(db, out);
}

// round 10
// speedup vs baseline: 1.0897x; 1.0897x over previous
#include <cuda_runtime.h>
#include <cuda_bf16.h>
#include <cstdint>

// Problem constants
#define B_  4
#define C_  256
#define H_  64
#define W_  64
#define O_  256
#define K2_ 9
#define PAD_ 2
#define DIL_ 2
#define CK_ (C_ * K2_)            // 2304
#define HW_ (H_ * W_)             // 4096
#define OUT_MAIN (B_ * O_ * HW_)  // 4194304
#define DW_ELEMS (O_ * C_ * K2_)  // 589824

#define SWZ(off) ((off) ^ (((off) >> 3) & 0x70))

// ---------------------------------------------------------------------------
// Scratch (device globals; no allocation allowed)
// ---------------------------------------------------------------------------
__device__ float g_off[B_ * 18 * HW_];            // clipped offsets (B,18,H,W)
__device__ float g_xT[B_ * HW_ * C_];             // x transposed: [b][hw][c]
__device__ unsigned char g_w[36 * 65536];         // bf16 hi/lo weight tiles, pre-swizzled

// ---------------------------------------------------------------------------
// helpers
// ---------------------------------------------------------------------------
__device__ __forceinline__ void ldsm4(uint32_t* r, uint32_t addr) {
    asm volatile("ldmatrix.sync.aligned.m8n8.x4.shared.b16 {%0,%1,%2,%3}, [%4];"
        : "=r"(r[0]), "=r"(r[1]), "=r"(r[2]), "=r"(r[3]) : "r"(addr));
}
__device__ __forceinline__ void mma16816(float* c, const uint32_t* a, const uint32_t* b) {
    asm volatile("mma.sync.aligned.m16n8k16.row.col.f32.bf16.bf16.f32 "
        "{%0,%1,%2,%3}, {%4,%5,%6,%7}, {%8,%9}, {%0,%1,%2,%3};"
        : "+f"(c[0]), "+f"(c[1]), "+f"(c[2]), "+f"(c[3])
        : "r"(a[0]), "r"(a[1]), "r"(a[2]), "r"(a[3]), "r"(b[0]), "r"(b[1]));
}
__device__ __forceinline__ uint32_t smem_u32(const void* p) {
    uint32_t a;
    asm("{ .reg .u64 t; cvta.to.shared.u64 t, %1; cvt.u32.u64 %0, t; }"
        : "=r"(a) : "l"(p));
    return a;
}
__device__ __forceinline__ uint32_t pack_bf16(float a, float b) {
    return ((uint32_t)__bfloat16_as_ushort(__float2bfloat16(b)) << 16) |
           (uint32_t)__bfloat16_as_ushort(__float2bfloat16(a));
}
__device__ __forceinline__ void cpasync16(uint32_t dst, const void* src) {
    asm volatile("cp.async.cg.shared.global [%0], [%1], 16;"
        :: "r"(dst), "l"(src) : "memory");
}

// ---------------------------------------------------------------------------
// Merged prologue kernel: roles by blockIdx.x (all 256 threads)
// ---------------------------------------------------------------------------
#define NB_T 4096
#define NB_O 256
#define NB_P 2304
#define PRO_SMEM 41472

__global__ __launch_bounds__(256) void prologue_kernel(
    const float* __restrict__ x, const float* __restrict__ ow,
    const float* __restrict__ ob, const float* __restrict__ dw,
    float* __restrict__ out_tail)
{
    extern __shared__ float sm[];
    const int bid = blockIdx.x;
    const int tid = threadIdx.x;

    if (bid < NB_T) {
        // ---- transpose ----
        __shared__ float ts[32][33];
        const int b = bid >> 10;
        const int tile = bid & 1023;
        const int c0 = (tile >> 7) * 32;
        const int hw0 = (tile & 127) * 32;
        const int tx = tid & 31, ty = tid >> 5;
        const float* xb = x + (size_t)b * C_ * HW_;
#pragma unroll
        for (int i = 0; i < 4; i++)
            ts[ty + i * 8][tx] = __ldg(xb + (size_t)(c0 + ty + i * 8) * HW_ + hw0 + tx);
        __syncthreads();
        float* dst = g_xT + (size_t)b * HW_ * C_;
#pragma unroll
        for (int i = 0; i < 4; i++)
            dst[(size_t)(hw0 + ty + i * 8) * C_ + c0 + tx] = ts[tx][ty + i * 8];
        return;
    }

    if (bid < NB_T + NB_O) {
        // ---- offset conv ----
        const int b2 = bid - NB_T;
        const int b = b2 >> 6;
        const int h = b2 & 63;
        const int g = tid >> 5;       // 0..7
        const int wq = tid & 31;
        const int w0 = wq * 2;

        float acc[18][2];
#pragma unroll
        for (int ch = 0; ch < 18; ch++) { acc[ch][0] = 0.f; acc[ch][1] = 0.f; }

        for (int r = 0; r < 4; r++) {
            __syncthreads();
            for (int i = tid; i < 64 * 162; i += 256) {
                int cc = i / 162;
                int j  = i - cc * 162;
                int ch = j / 9;
                int t  = j - ch * 9;
                sm[i] = ow[ch * CK_ + (r * 64 + cc) * 9 + t];
            }
            __syncthreads();

#pragma unroll
            for (int q = 0; q < 8; q++) {
                const int cc = g * 8 + q;
                const int c  = r * 64 + cc;
                const float* xp = x + ((size_t)b * C_ + c) * HW_;
                float xv[3][4];
#pragma unroll
                for (int ry = 0; ry < 3; ry++) {
                    int yy = h - 1 + ry;
                    bool yok = (yy >= 0) & (yy < H_);
#pragma unroll
                    for (int cx = 0; cx < 4; cx++) {
                        int xx = w0 - 1 + cx;
                        bool ok = yok & (xx >= 0) & (xx < W_);
                        xv[ry][cx] = ok ? __ldg(xp + yy * W_ + xx) : 0.0f;
                    }
                }
                const float* wc = sm + cc * 162;
#pragma unroll
                for (int ch = 0; ch < 18; ch++) {
#pragma unroll
                    for (int ky = 0; ky < 3; ky++) {
#pragma unroll
                        for (int kx = 0; kx < 3; kx++) {
                            float wv = wc[ch * 9 + ky * 3 + kx];
                            acc[ch][0] = fmaf(wv, xv[ky][kx],     acc[ch][0]);
                            acc[ch][1] = fmaf(wv, xv[ky][kx + 1], acc[ch][1]);
                        }
                    }
                }
            }
        }
        __syncthreads();
#pragma unroll
        for (int ch = 0; ch < 18; ch++) {
            sm[(g * 18 + ch) * 64 + w0]     = acc[ch][0];
            sm[(g * 18 + ch) * 64 + w0 + 1] = acc[ch][1];
        }
        __syncthreads();
        for (int i = tid; i < 18 * 64; i += 256) {
            int ch = i >> 6;
            int w  = i & 63;
            float s = ob[ch];
#pragma unroll
            for (int gg = 0; gg < 8; gg++) s += sm[(gg * 18 + ch) * 64 + w];
            s = fminf(fmaxf(s, -1.0f), 1.0f);
            g_off[((size_t)b * 18 + ch) * HW_ + h * W_ + w] = s;
        }
        return;
    }

    // ---- weight prep + tail copy ----
    {
        int id = (bid - NB_T - NB_O) * 256 + tid;
        out_tail[id] = dw[id];
        int k = id & 63;
        int o = (id >> 6) & 255;
        int t = id >> 14;            // 0..35
        int n = t >> 2;
        int cc = t & 3;
        int c = cc * 64 + k;
        float v = __ldg(dw + o * CK_ + c * 9 + n);
        __nv_bfloat16 hi = __float2bfloat16(v);
        __nv_bfloat16 lo = __float2bfloat16(v - __bfloat162float(hi));
        uint32_t sw = SWZ((uint32_t)(o * 128 + k * 2));
        size_t base = (size_t)t * 65536;
        *(__nv_bfloat16*)(g_w + base + sw)         = hi;
        *(__nv_bfloat16*)(g_w + base + 32768 + sw) = lo;
    }
}

// ---------------------------------------------------------------------------
// Fused deform sampling + bf16-split mma.sync GEMM, software pipelined.
// Grid = 128 blocks (b, h2): N=128 pixels (2 rows), M=256 o, K=2304 (36 x 64).
// 256 threads = 8 warps; warp tile 64(M) x 64(N) -> acc 128 regs, reg budget
// 256/thread so fragment loads pipeline ahead of HMMAs (R6 was capped at 128).
// Double-buffered A (cp.async) and B (register-gather overlapped with MMA).
// ---------------------------------------------------------------------------
#define OFF_A    0        // 2 buf x [2 comp][256][64] bf16 = 2 x 65536
#define OFF_B    131072   // 2 buf x [2 comp][128][64] bf16 = 2 x 32768
#define OFF_SWT  196608   // float [9*128][4]  = 18432
#define OFF_SIDX 215040   // short [9*128][4]  = 9216
#define FUSED_SMEM 224256

__global__ __launch_bounds__(256, 1) void fused_deform_mma_kernel(
    const float* __restrict__ db, float* __restrict__ out)
{
    extern __shared__ char smem[];
    const uint32_t sb = smem_u32(smem);
    const int tid = threadIdx.x;
    const int wid = tid >> 5;
    const int lid = tid & 31;
    const int b  = blockIdx.x >> 5;
    const int h2 = blockIdx.x & 31;

    // ---- sampling metadata: 9 taps x 128 pixels ----
    float* swt  = (float*)(smem + OFF_SWT);
    short* sidx = (short*)(smem + OFF_SIDX);
    for (int task = tid; task < 9 * 128; task += 256) {
        int n = task >> 7;
        int p = task & 127;
        int h = h2 * 2 + (p >> 6);
        int w = p & 63;
        float dy = g_off[((size_t)b * 18 + 2 * n)     * HW_ + h * W_ + w];
        float dx = g_off[((size_t)b * 18 + 2 * n + 1) * HW_ + h * W_ + w];
        float py = dy + (float)(-PAD_ + (n / 3) * DIL_ + h);
        float px = dx + (float)(-PAD_ + (n % 3) * DIL_ + w);
        float y0f = floorf(py);
        float x0f = floorf(px);
        float ly1 = py - y0f, lx1 = px - x0f;
        float ly0 = 1.0f - ly1, lx0 = 1.0f - lx1;
        int y0 = (int)y0f, x0 = (int)x0f;
#pragma unroll
        for (int j = 0; j < 4; j++) {
            int yy = y0 + (j >> 1);
            int xx = x0 + (j & 1);
            float wgt = ((j >> 1) ? ly1 : ly0) * ((j & 1) ? lx1 : lx0);
            bool ok = (yy >= 0) & (yy < H_) & (xx >= 0) & (xx < W_);
            int yi = min(max(yy, 0), H_ - 1);
            int xi = min(max(xx, 0), W_ - 1);
            sidx[task * 4 + j] = (short)(yi * W_ + xi);
            swt [task * 4 + j] = ok ? wgt : 0.0f;
        }
    }
    __syncthreads();

    const float* xT = g_xT + (size_t)b * HW_ * C_;
    const int ch4 = tid & 15;          // channel group of 4 (fixed per thread)
    const int pixB = tid >> 4;         // base pixel selector 0..15

    const int wm = wid >> 1;           // 0..3 : o block of 64
    const int wn = wid & 1;            // 0..1 : pixel block of 64
    const int aRow = wm * 64 + (lid & 15);
    const int aKad = (lid >> 4) * 16;
    const int bRow = wn * 64 + ((lid >> 4) & 1) * 8 + (lid & 7);
    const int bKad = ((lid >> 3) & 1) * 16;

    float acc[4][8][4];
#pragma unroll
    for (int i = 0; i < 4; i++)
#pragma unroll
        for (int j = 0; j < 8; j++)
#pragma unroll
            for (int q = 0; q < 4; q++) acc[i][j][q] = 0.0f;

    // ---- prologue: stage chunk 0 ----
    {
        uint32_t dstA = sb + OFF_A;
        const char* srcA = (const char*)g_w;
#pragma unroll
        for (int i = 0; i < 16; i++)
            cpasync16(dstA + (tid + i * 256) * 16, srcA + (size_t)(tid + i * 256) * 16);
        asm volatile("cp.async.commit_group;" ::: "memory");
#pragma unroll
        for (int it = 0; it < 8; it++) {
            int id = tid + it * 256;          // 2048 tasks
            int c4 = id & 15;
            int p  = id >> 4;
            const float4 wt = *(const float4*)(swt + p * 4);
            const short* si = sidx + p * 4;
            const float* xb = xT + c4 * 4;
            float4 v0 = __ldg((const float4*)(xb + ((int)si[0] << 8)));
            float4 v1 = __ldg((const float4*)(xb + ((int)si[1] << 8)));
            float4 v2 = __ldg((const float4*)(xb + ((int)si[2] << 8)));
            float4 v3 = __ldg((const float4*)(xb + ((int)si[3] << 8)));
            float s0 = wt.x * v0.x + wt.y * v1.x + wt.z * v2.x + wt.w * v3.x;
            float s1 = wt.x * v0.y + wt.y * v1.y + wt.z * v2.y + wt.w * v3.y;
            float s2 = wt.x * v0.z + wt.y * v1.z + wt.z * v2.z + wt.w * v3.z;
            float s3 = wt.x * v0.w + wt.y * v1.w + wt.z * v2.w + wt.w * v3.w;
            uint32_t h0 = pack_bf16(s0, s1), h1 = pack_bf16(s2, s3);
            float r0 = s0 - __bfloat162float(__float2bfloat16(s0));
            float r1 = s1 - __bfloat162float(__float2bfloat16(s1));
            float r2 = s2 - __bfloat162float(__float2bfloat16(s2));
            float r3 = s3 - __bfloat162float(__float2bfloat16(s3));
            uint32_t l0 = pack_bf16(r0, r1), l1 = pack_bf16(r2, r3);
            uint32_t sw = SWZ((uint32_t)(p * 128 + c4 * 8));
            *(uint2*)(smem + OFF_B + sw)         = make_uint2(h0, h1);
            *(uint2*)(smem + OFF_B + 16384 + sw) = make_uint2(l0, l1);
        }
    }

    for (int t = 0; t < 36; t++) {
        const uint32_t bufT = (uint32_t)(t & 1);
        const uint32_t bufN = bufT ^ 1;
        const bool more = (t < 35);

        // bar1: all reads of buffer bufN's OLD content complete
        __syncthreads();

        if (more) {
            uint32_t dstA = sb + OFF_A + bufN * 65536;
            const char* srcA = (const char*)(g_w + (size_t)(t + 1) * 65536);
#pragma unroll
            for (int i = 0; i < 16; i++)
                cpasync16(dstA + (tid + i * 256) * 16, srcA + (size_t)(tid + i * 256) * 16);
            asm volatile("cp.async.commit_group;" ::: "memory");
            asm volatile("cp.async.wait_group 1;" ::: "memory");
        } else {
            asm volatile("cp.async.wait_group 0;" ::: "memory");
        }

        // bar2: everyone's A(t) landed; B(t) STS from iter t-1 visible
        __syncthreads();

        const uint32_t aBaseH = sb + OFF_A + bufT * 65536;
        const uint32_t aBaseL = aBaseH + 32768;
        const uint32_t bBaseH = sb + OFF_B + bufT * 32768;
        const uint32_t bBaseL = bBaseH + 16384;
        char* bDst = smem + OFF_B + bufN * 32768;

        const int nN = (t + 1) >> 2;
        const int cN = ((t + 1) & 3) * 64;

#pragma unroll
        for (int ph = 0; ph < 4; ph++) {
            // two gather tasks per thread per phase (issued before MMA)
            float4 va0, va1, va2, va3, wa;
            float4 vb0, vb1, vb2, vb3, wb;
            int pA = pixB + ph * 32;          // pixels 0..31 region
            int pB = pA + 16;                 // pixels 16..47... (pixB<16)
            if (more) {
                int taskA = nN * 128 + pA;
                wa = *(const float4*)(swt + taskA * 4);
                const short* siA = sidx + taskA * 4;
                const float* xb = xT + cN + ch4 * 4;
                va0 = __ldg((const float4*)(xb + ((int)siA[0] << 8)));
                va1 = __ldg((const float4*)(xb + ((int)siA[1] << 8)));
                va2 = __ldg((const float4*)(xb + ((int)siA[2] << 8)));
                va3 = __ldg((const float4*)(xb + ((int)siA[3] << 8)));
                int taskB = nN * 128 + pB;
                wb = *(const float4*)(swt + taskB * 4);
                const short* siB = sidx + taskB * 4;
                vb0 = __ldg((const float4*)(xb + ((int)siB[0] << 8)));
                vb1 = __ldg((const float4*)(xb + ((int)siB[1] << 8)));
                vb2 = __ldg((const float4*)(xb + ((int)siB[2] << 8)));
                vb3 = __ldg((const float4*)(xb + ((int)siB[3] << 8)));
            }

            // MMA k-step ph of chunk t (warp tile 64x64)
            {
                uint32_t bh[16], bl[16];
#pragma unroll
                for (int pair = 0; pair < 4; pair++) {
                    uint32_t off = SWZ((uint32_t)((bRow + pair * 16) * 128 + ph * 32 + bKad));
                    ldsm4(bh + pair * 4, bBaseH + off);
                    ldsm4(bl + pair * 4, bBaseL + off);
                }
#pragma unroll
                for (int mt = 0; mt < 4; mt++) {
                    uint32_t offA = SWZ((uint32_t)((aRow + mt * 16) * 128 + ph * 32 + aKad));
                    uint32_t ah[4], al[4];
                    ldsm4(ah, aBaseH + offA);
#pragma unroll
                    for (int j = 0; j < 8; j++) {
                        mma16816(acc[mt][j], ah, bh + j * 2);
                        mma16816(acc[mt][j], ah, bl + j * 2);
                    }
                    ldsm4(al, aBaseL + offA);
#pragma unroll
                    for (int j = 0; j < 8; j++)
                        mma16816(acc[mt][j], al, bh + j * 2);
                }
            }

            if (more) {
                // pack + STS task A
                {
                    float s0 = wa.x * va0.x + wa.y * va1.x + wa.z * va2.x + wa.w * va3.x;
                    float s1 = wa.x * va0.y + wa.y * va1.y + wa.z * va2.y + wa.w * va3.y;
                    float s2 = wa.x * va0.z + wa.y * va1.z + wa.z * va2.z + wa.w * va3.z;
                    float s3 = wa.x * va0.w + wa.y * va1.w + wa.z * va2.w + wa.w * va3.w;
                    uint32_t h0 = pack_bf16(s0, s1), h1 = pack_bf16(s2, s3);
                    float r0 = s0 - __bfloat162float(__float2bfloat16(s0));
                    float r1 = s1 - __bfloat162float(__float2bfloat16(s1));
                    float r2 = s2 - __bfloat162float(__float2bfloat16(s2));
                    float r3 = s3 - __bfloat162float(__float2bfloat16(s3));
                    uint32_t l0 = pack_bf16(r0, r1), l1 = pack_bf16(r2, r3);
                    uint32_t sw = SWZ((uint32_t)(pA * 128 + ch4 * 8));
                    *(uint2*)(bDst + sw)         = make_uint2(h0, h1);
                    *(uint2*)(bDst + 16384 + sw) = make_uint2(l0, l1);
                }
                // pack + STS task B
                {
                    float s0 = wb.x * vb0.x + wb.y * vb1.x + wb.z * vb2.x + wb.w * vb3.x;
                    float s1 = wb.x * vb0.y + wb.y * vb1.y + wb.z * vb2.y + wb.w * vb3.y;
                    float s2 = wb.x * vb0.z + wb.y * vb1.z + wb.z * vb2.z + wb.w * vb3.z;
                    float s3 = wb.x * vb0.w + wb.y * vb1.w + wb.z * vb2.w + wb.w * vb3.w;
                    uint32_t h0 = pack_bf16(s0, s1), h1 = pack_bf16(s2, s3);
                    float r0 = s0 - __bfloat162float(__float2bfloat16(s0));
                    float r1 = s1 - __bfloat162float(__float2bfloat16(s1));
                    float r2 = s2 - __bfloat162float(__float2bfloat16(s2));
                    float r3 = s3 - __bfloat162float(__float2bfloat16(s3));
                    uint32_t l0 = pack_bf16(r0, r1), l1 = pack_bf16(r2, r3);
                    uint32_t sw = SWZ((uint32_t)(pB * 128 + ch4 * 8));
                    *(uint2*)(bDst + sw)         = make_uint2(h0, h1);
                    *(uint2*)(bDst + 16384 + sw) = make_uint2(l0, l1);
                }
            }
        }
    }

    // ---- epilogue: bias + store ----
#pragma unroll
    for (int mt = 0; mt < 4; mt++) {
        int o0 = wm * 64 + mt * 16 + (lid >> 2);
        float b0v = __ldg(db + o0);
        float b1v = __ldg(db + o0 + 8);
#pragma unroll
        for (int j = 0; j < 8; j++) {
            int pixel = wn * 64 + j * 8 + (lid & 3) * 2;
            int row = pixel >> 6, col = pixel & 63;
            float* p0 = out + ((size_t)(b * O_ + o0)) * HW_
                            + (size_t)(h2 * 2 + row) * W_ + col;
            *(float2*)p0 = make_float2(acc[mt][j][0] + b0v, acc[mt][j][1] + b0v);
            float* p1 = p0 + (size_t)8 * HW_;
            *(float2*)p1 = make_float2(acc[mt][j][2] + b1v, acc[mt][j][3] + b1v);
        }
    }
}

// ---------------------------------------------------------------------------
extern "C" void kernel_launch(void* const* d_in, const int* in_sizes, int n_in,
                              void* d_out, int out_size)
{
    const float* x  = (const float*)d_in[0];
    const float* ow = (const float*)d_in[1];
    const float* ob = (const float*)d_in[2];
    const float* dw = (const float*)d_in[3];
    const float* db = (const float*)d_in[4];
    float* out = (float*)d_out;

    cudaFuncSetAttribute(prologue_kernel,
                         cudaFuncAttributeMaxDynamicSharedMemorySize, PRO_SMEM);
    cudaFuncSetAttribute(fused_deform_mma_kernel,
                         cudaFuncAttributeMaxDynamicSharedMemorySize, FUSED_SMEM);

    prologue_kernel<<<NB_T + NB_O + NB_P, 256, PRO_SMEM>>>(x, ow, ob, dw, out + OUT_MAIN);
    fused_deform_mma_kernel<<<B_ * 32, 256, FUSED_SMEM>>>(db, out);
}